// round 1
// baseline (speedup 1.0000x reference)
#include <cuda_runtime.h>

// GAE reverse scan: adv_t = delta_t + (gamma*lambda*nt_t) * adv_{t+1}
//   delta_t = r_t + gamma * v_{t+1} * nt_t - v_t,  nt_t = 1 - done_{t+1}
//   (v_T = 0, done_T = 1)
// Output: d_out[0 : T*N]     = advantages
//         d_out[T*N : 2*T*N] = advantages + values  (returns)

#define T_DIM   2048
#define N_DIM   4096
#define CHUNKS  32
#define L_CHUNK (T_DIM / CHUNKS)   // 64 rows per chunk

#define GAMMA_F 0.99f
#define GL_F    (0.99f * 0.95f)

// Scratch (no cudaMalloc allowed): per-(chunk, column) affine coefficients
// and carries. 3 * 32 * 4096 * 4B = 1.5 MB.
__device__ float g_A[CHUNKS * N_DIM];
__device__ float g_B[CHUNKS * N_DIM];
__device__ float g_carry[CHUNKS * N_DIM];

// ---------------------------------------------------------------------------
// Pass 1: per-chunk affine reduction.  adv_top_of_chunk = A + B * carry_in.
// ---------------------------------------------------------------------------
__global__ __launch_bounds__(256)
void gae_pass1(const float* __restrict__ rew,
               const float* __restrict__ val,
               const float* __restrict__ don)
{
    const int n = blockIdx.x * blockDim.x + threadIdx.x;   // column
    const int k = blockIdx.y;                              // chunk
    const int lo = k * L_CHUNK;
    const int hi = lo + L_CHUNK - 1;

    float v_next, d_next;
    if (hi == T_DIM - 1) {
        v_next = 0.0f;
        d_next = 1.0f;
    } else {
        v_next = val[(hi + 1) * N_DIM + n];
        d_next = don[(hi + 1) * N_DIM + n];
    }

    float A = 0.0f;
    float B = 1.0f;

    #pragma unroll 8
    for (int t = hi; t >= lo; --t) {
        const int idx = t * N_DIM + n;
        const float rt = rew[idx];
        const float vt = val[idx];
        const float dt = don[idx];

        const float nt    = 1.0f - d_next;
        const float delta = rt + GAMMA_F * v_next * nt - vt;
        const float c     = GL_F * nt;

        A = fmaf(c, A, delta);   // A = delta + c*A
        B = c * B;

        v_next = vt;
        d_next = dt;
    }

    g_A[k * N_DIM + n] = A;
    g_B[k * N_DIM + n] = B;
}

// ---------------------------------------------------------------------------
// Mid pass: compose the 32 chunk-affine maps per column (reverse order),
// producing the carry entering each chunk.
// ---------------------------------------------------------------------------
__global__ __launch_bounds__(256)
void gae_mid()
{
    const int n = blockIdx.x * blockDim.x + threadIdx.x;

    float carry = 0.0f;   // adv beyond the last row is 0
    #pragma unroll
    for (int k = CHUNKS - 1; k >= 0; --k) {
        const int idx = k * N_DIM + n;
        g_carry[idx] = carry;
        carry = fmaf(g_B[idx], carry, g_A[idx]);  // adv at top of chunk k
    }
}

// ---------------------------------------------------------------------------
// Pass 2: re-scan each chunk with its true carry; emit advantages & returns.
// ---------------------------------------------------------------------------
__global__ __launch_bounds__(256)
void gae_pass2(const float* __restrict__ rew,
               const float* __restrict__ val,
               const float* __restrict__ don,
               float* __restrict__ out)
{
    const int n = blockIdx.x * blockDim.x + threadIdx.x;
    const int k = blockIdx.y;
    const int lo = k * L_CHUNK;
    const int hi = lo + L_CHUNK - 1;

    float v_next, d_next;
    if (hi == T_DIM - 1) {
        v_next = 0.0f;
        d_next = 1.0f;
    } else {
        v_next = val[(hi + 1) * N_DIM + n];
        d_next = don[(hi + 1) * N_DIM + n];
    }

    float adv = g_carry[k * N_DIM + n];

    float* __restrict__ out_adv = out;
    float* __restrict__ out_ret = out + (size_t)T_DIM * N_DIM;

    #pragma unroll 8
    for (int t = hi; t >= lo; --t) {
        const int idx = t * N_DIM + n;
        const float rt = rew[idx];
        const float vt = val[idx];
        const float dt = don[idx];

        const float nt    = 1.0f - d_next;
        const float delta = rt + GAMMA_F * v_next * nt - vt;
        const float c     = GL_F * nt;

        adv = fmaf(c, adv, delta);

        out_adv[idx] = adv;
        out_ret[idx] = adv + vt;

        v_next = vt;
        d_next = dt;
    }
}

// ---------------------------------------------------------------------------
extern "C" void kernel_launch(void* const* d_in, const int* in_sizes, int n_in,
                              void* d_out, int out_size)
{
    const float* rew = (const float*)d_in[0];
    const float* val = (const float*)d_in[1];
    const float* don = (const float*)d_in[2];
    float* out = (float*)d_out;

    dim3 block(256);
    dim3 grid1(N_DIM / 256, CHUNKS);

    gae_pass1<<<grid1, block>>>(rew, val, don);
    gae_mid<<<N_DIM / 256, block>>>();
    gae_pass2<<<grid1, block>>>(rew, val, don, out);
}